// round 8
// baseline (speedup 1.0000x reference)
#include <cuda_runtime.h>

// LIF neuron forward: X [B=64, T=32, N=65536] f32 -> spikes, same shape.
// Recurrence per (b,n): mem = mem + (x - mem)/TAU (TAU=0.5); spike = mem > 1;
// mem = spike ? 0 : mem.  Pure HBM-bound streaming kernel.
//
// R4: (256,8) regs=32  -> 161.9us, DRAM 84.0%
// R5: ldcs/stcs regs=20 -> 165.0us, 80.4% (MLP collapse, reverted)
// R6: (256,6) regs=40  -> 160.1us, DRAM 84.3%  (MLP x occ traded ~flat)
// R7 change: grow the MLP *product*: 2 float4 columns per thread,
// __launch_bounds__(256,4) (reg cap 64). ~384 outstanding lines/SM vs ~288.
// If DRAM stays <=85%, ~6.7TB/s is the mixed-R/W ceiling -> freeze at R6.
//
// fmaf(x-m, 2, m) is bit-identical to the reference's unfused form
// because *2 is exact in fp32; spike decisions cannot flip.

namespace {
constexpr int B  = 64;
constexpr int T  = 32;
constexpr int N  = 65536;
constexpr int N4 = N / 4;                 // float4 lanes per (b,t) row: 16384
constexpr float VTH = 1.0f;
}

__global__ __launch_bounds__(256, 4)
void lif_kernel(const float4* __restrict__ X, float4* __restrict__ out) {
    // Each thread handles TWO consecutive float4 columns: 2*tid, 2*tid+1.
    const unsigned tid = blockIdx.x * 256u + threadIdx.x;   // 0 .. B*N4/2-1
    const unsigned col = tid * 2u;              // first float4 column index
    const unsigned b = col >> 14;               // col / N4   (N4 = 2^14)
    const unsigned n = col & (N4 - 1);          // col % N4

    const size_t base = (size_t)b * (size_t)T * (size_t)N4 + n;
    const float4* __restrict__ xp = X + base;
    float4* __restrict__ op = out + base;

    float a0 = 0.f, a1 = 0.f, a2 = 0.f, a3 = 0.f;   // membrane, column col
    float b0 = 0.f, b1 = 0.f, b2 = 0.f, b3 = 0.f;   // membrane, column col+1

#pragma unroll
    for (int t = 0; t < T; ++t) {
        const float4 xa = xp[(size_t)t * N4];
        const float4 xb = xp[(size_t)t * N4 + 1];

        a0 = fmaf(xa.x - a0, 2.0f, a0);
        a1 = fmaf(xa.y - a1, 2.0f, a1);
        a2 = fmaf(xa.z - a2, 2.0f, a2);
        a3 = fmaf(xa.w - a3, 2.0f, a3);
        b0 = fmaf(xb.x - b0, 2.0f, b0);
        b1 = fmaf(xb.y - b1, 2.0f, b1);
        b2 = fmaf(xb.z - b2, 2.0f, b2);
        b3 = fmaf(xb.w - b3, 2.0f, b3);

        const bool sa0 = a0 > VTH, sa1 = a1 > VTH, sa2 = a2 > VTH, sa3 = a3 > VTH;
        const bool sb0 = b0 > VTH, sb1 = b1 > VTH, sb2 = b2 > VTH, sb3 = b3 > VTH;

        float4 pa, pb;
        pa.x = sa0 ? 1.0f : 0.0f;  pa.y = sa1 ? 1.0f : 0.0f;
        pa.z = sa2 ? 1.0f : 0.0f;  pa.w = sa3 ? 1.0f : 0.0f;
        pb.x = sb0 ? 1.0f : 0.0f;  pb.y = sb1 ? 1.0f : 0.0f;
        pb.z = sb2 ? 1.0f : 0.0f;  pb.w = sb3 ? 1.0f : 0.0f;

        a0 = sa0 ? 0.0f : a0;  a1 = sa1 ? 0.0f : a1;
        a2 = sa2 ? 0.0f : a2;  a3 = sa3 ? 0.0f : a3;
        b0 = sb0 ? 0.0f : b0;  b1 = sb1 ? 0.0f : b1;
        b2 = sb2 ? 0.0f : b2;  b3 = sb3 ? 0.0f : b3;

        op[(size_t)t * N4]     = pa;
        op[(size_t)t * N4 + 1] = pb;
    }
}

extern "C" void kernel_launch(void* const* d_in, const int* in_sizes, int n_in,
                              void* d_out, int out_size) {
    (void)in_sizes; (void)n_in; (void)out_size;
    const float4* X = (const float4*)d_in[0];
    float4* out = (float4*)d_out;

    const int total_threads = B * N4 / 2;      // 524,288
    const int block = 256;
    const int grid = total_threads / block;    // 2048
    lif_kernel<<<grid, block>>>(X, out);
}

// round 13
// speedup vs baseline: 1.1029x; 1.1029x over previous
#include <cuda_runtime.h>

// LIF neuron forward: X [B=64, T=32, N=65536] f32 -> spikes, same shape.
// Recurrence per (b,n): mem = mem + (x - mem)/TAU (TAU=0.5); spike = mem > 1;
// mem = spike ? 0 : mem.  Pure HBM-bound streaming kernel.
//
// R4: 1-col (256,8) regs=32 -> 161.9us, DRAM 84.0%
// R5: ldcs/stcs regs=20     -> 165.0us, 80.4% (MLP collapse)
// R6: 1-col (256,6) regs=40 -> 160.1us, DRAM 84.3%
// R8: 2-col (256,4) regs=64 CAP -> SPILLED: 3.1GB traffic, 453us,
//     but DRAM hit 88.8% of spec => MLP lever real, reg cap was the bug.
// R10: 2-col with __launch_bounds__(256,2) (cap 128): ptxas allocates
// naturally (~80 regs expected -> occ 3 anyway), zero spill risk.
// Occupancy follows ACTUAL regs, so (256,2) dominates forcing cap 80.
//
// fmaf(x-m, 2, m) is bit-identical to the reference's unfused form
// because *2 is exact in fp32; spike decisions cannot flip.

namespace {
constexpr int B  = 64;
constexpr int T  = 32;
constexpr int N  = 65536;
constexpr int N4 = N / 4;                 // float4 lanes per (b,t) row: 16384
constexpr float VTH = 1.0f;
}

__global__ __launch_bounds__(256, 2)
void lif_kernel(const float4* __restrict__ X, float4* __restrict__ out) {
    // Each thread handles TWO consecutive float4 columns: 2*tid, 2*tid+1.
    const unsigned tid = blockIdx.x * 256u + threadIdx.x;   // 0 .. B*N4/2-1
    const unsigned col = tid * 2u;              // first float4 column index
    const unsigned b = col >> 14;               // col / N4   (N4 = 2^14)
    const unsigned n = col & (N4 - 1);          // col % N4

    const size_t base = (size_t)b * (size_t)T * (size_t)N4 + n;
    const float4* __restrict__ xp = X + base;
    float4* __restrict__ op = out + base;

    float a0 = 0.f, a1 = 0.f, a2 = 0.f, a3 = 0.f;   // membrane, column col
    float b0 = 0.f, b1 = 0.f, b2 = 0.f, b3 = 0.f;   // membrane, column col+1

#pragma unroll
    for (int t = 0; t < T; ++t) {
        const float4 xa = xp[(size_t)t * N4];
        const float4 xb = xp[(size_t)t * N4 + 1];

        a0 = fmaf(xa.x - a0, 2.0f, a0);
        a1 = fmaf(xa.y - a1, 2.0f, a1);
        a2 = fmaf(xa.z - a2, 2.0f, a2);
        a3 = fmaf(xa.w - a3, 2.0f, a3);
        b0 = fmaf(xb.x - b0, 2.0f, b0);
        b1 = fmaf(xb.y - b1, 2.0f, b1);
        b2 = fmaf(xb.z - b2, 2.0f, b2);
        b3 = fmaf(xb.w - b3, 2.0f, b3);

        const bool sa0 = a0 > VTH, sa1 = a1 > VTH, sa2 = a2 > VTH, sa3 = a3 > VTH;
        const bool sb0 = b0 > VTH, sb1 = b1 > VTH, sb2 = b2 > VTH, sb3 = b3 > VTH;

        float4 pa, pb;
        pa.x = sa0 ? 1.0f : 0.0f;  pa.y = sa1 ? 1.0f : 0.0f;
        pa.z = sa2 ? 1.0f : 0.0f;  pa.w = sa3 ? 1.0f : 0.0f;
        pb.x = sb0 ? 1.0f : 0.0f;  pb.y = sb1 ? 1.0f : 0.0f;
        pb.z = sb2 ? 1.0f : 0.0f;  pb.w = sb3 ? 1.0f : 0.0f;

        a0 = sa0 ? 0.0f : a0;  a1 = sa1 ? 0.0f : a1;
        a2 = sa2 ? 0.0f : a2;  a3 = sa3 ? 0.0f : a3;
        b0 = sb0 ? 0.0f : b0;  b1 = sb1 ? 0.0f : b1;
        b2 = sb2 ? 0.0f : b2;  b3 = sb3 ? 0.0f : b3;

        op[(size_t)t * N4]     = pa;
        op[(size_t)t * N4 + 1] = pb;
    }
}

extern "C" void kernel_launch(void* const* d_in, const int* in_sizes, int n_in,
                              void* d_out, int out_size) {
    (void)in_sizes; (void)n_in; (void)out_size;
    const float4* X = (const float4*)d_in[0];
    float4* out = (float4*)d_out;

    const int total_threads = B * N4 / 2;      // 524,288
    const int block = 256;
    const int grid = total_threads / block;    // 2048
    lif_kernel<<<grid, block>>>(X, out);
}

// round 15
// speedup vs baseline: 2.8175x; 2.5547x over previous
#include <cuda_runtime.h>

// LIF neuron forward: X [B=64, T=32, N=65536] f32 -> spikes, same shape.
// Recurrence per (b,n): mem = mem + (x - mem)/TAU (TAU=0.5); spike = mem > 1;
// mem = spike ? 0 : mem.  Pure HBM-bound streaming kernel.
//
// R4:  1-col (256,8) regs=32 -> 161.9us, DRAM 84.0% (all useful)
// R6:  1-col (256,6) regs=40 -> 160.1us, DRAM 84.3%  <-- best
// R8:  2-col ADJACENT (256,4) -> 453us, ~2.9x traffic
// R13: 2-col ADJACENT (256,2) regs=94, NO spill -> 411us, ~2.6x traffic.
//   => amplification is the interleaved 32B-stride pattern itself (partial
//      sector fetch/RMW waste), NOT spill. "MLP helps" evidence retracted.
// R14: clean discriminator: 2 columns per thread but DENSE per warp —
// thread owns flat column tid and tid+524288 (two independent contiguous
// streams). Warp-level access identical to the 160us 1-col kernels; only
// per-thread MLP doubles. MLP-limited -> ~150us; ceiling -> ~160us.
//
// fmaf(x-m, 2, m) is bit-identical to the reference's unfused form
// because *2 is exact in fp32; spike decisions cannot flip.

namespace {
constexpr int B  = 64;
constexpr int T  = 32;
constexpr int N  = 65536;
constexpr int N4 = N / 4;                 // float4 lanes per (b,t) row: 16384
constexpr int TOTAL_COLS = B * N4;        // 1,048,576 flat float4 columns
constexpr int HALF = TOTAL_COLS / 2;      // 524,288
constexpr float VTH = 1.0f;
}

__global__ __launch_bounds__(256, 2)
void lif_kernel(const float4* __restrict__ X, float4* __restrict__ out) {
    // Two DENSE streams: flat column tid (stream A) and tid+HALF (stream B).
    const unsigned tid = blockIdx.x * 256u + threadIdx.x;   // 0 .. HALF-1

    // Stream A: column ca -> (b, n)
    const unsigned ca = tid;
    const unsigned ba = ca >> 14;
    const unsigned na = ca & (N4 - 1);
    const size_t baseA = (size_t)ba * (size_t)T * (size_t)N4 + na;

    // Stream B: column cb = ca + HALF -> (b+32, n)
    const unsigned cb = ca + (unsigned)HALF;
    const unsigned bb = cb >> 14;
    const unsigned nb = cb & (N4 - 1);
    const size_t baseB = (size_t)bb * (size_t)T * (size_t)N4 + nb;

    const float4* __restrict__ xpa = X + baseA;
    const float4* __restrict__ xpb = X + baseB;
    float4* __restrict__ opa = out + baseA;
    float4* __restrict__ opb = out + baseB;

    float a0 = 0.f, a1 = 0.f, a2 = 0.f, a3 = 0.f;   // membrane, stream A
    float b0 = 0.f, b1 = 0.f, b2 = 0.f, b3 = 0.f;   // membrane, stream B

#pragma unroll
    for (int t = 0; t < T; ++t) {
        const float4 xa = xpa[(size_t)t * N4];
        const float4 xb = xpb[(size_t)t * N4];

        a0 = fmaf(xa.x - a0, 2.0f, a0);
        a1 = fmaf(xa.y - a1, 2.0f, a1);
        a2 = fmaf(xa.z - a2, 2.0f, a2);
        a3 = fmaf(xa.w - a3, 2.0f, a3);
        b0 = fmaf(xb.x - b0, 2.0f, b0);
        b1 = fmaf(xb.y - b1, 2.0f, b1);
        b2 = fmaf(xb.z - b2, 2.0f, b2);
        b3 = fmaf(xb.w - b3, 2.0f, b3);

        const bool sa0 = a0 > VTH, sa1 = a1 > VTH, sa2 = a2 > VTH, sa3 = a3 > VTH;
        const bool sb0 = b0 > VTH, sb1 = b1 > VTH, sb2 = b2 > VTH, sb3 = b3 > VTH;

        float4 pa, pb;
        pa.x = sa0 ? 1.0f : 0.0f;  pa.y = sa1 ? 1.0f : 0.0f;
        pa.z = sa2 ? 1.0f : 0.0f;  pa.w = sa3 ? 1.0f : 0.0f;
        pb.x = sb0 ? 1.0f : 0.0f;  pb.y = sb1 ? 1.0f : 0.0f;
        pb.z = sb2 ? 1.0f : 0.0f;  pb.w = sb3 ? 1.0f : 0.0f;

        a0 = sa0 ? 0.0f : a0;  a1 = sa1 ? 0.0f : a1;
        a2 = sa2 ? 0.0f : a2;  a3 = sa3 ? 0.0f : a3;
        b0 = sb0 ? 0.0f : b0;  b1 = sb1 ? 0.0f : b1;
        b2 = sb2 ? 0.0f : b2;  b3 = sb3 ? 0.0f : b3;

        opa[(size_t)t * N4] = pa;
        opb[(size_t)t * N4] = pb;
    }
}

extern "C" void kernel_launch(void* const* d_in, const int* in_sizes, int n_in,
                              void* d_out, int out_size) {
    (void)in_sizes; (void)n_in; (void)out_size;
    const float4* X = (const float4*)d_in[0];
    float4* out = (float4*)d_out;

    const int total_threads = HALF;            // 524,288
    const int block = 256;
    const int grid = total_threads / block;    // 2048
    lif_kernel<<<grid, block>>>(X, out);
}